// round 14
// baseline (speedup 1.0000x reference)
#include <cuda_runtime.h>
#include <cuda_fp16.h>
#include <math.h>
#include <stdint.h>

#define N_NODES 50000
#define D 128
#define EPS 1e-5f
#define E_MAX 800000

// padded fp16 tile: rows x 64 cols, row stride 72 elems (144B = 9*16B -> bank rotate)
#define TROW 144
#define TILE_BYTES (128 * TROW)   // 18432
#define PADROWS 50048             // 391 tiles * 128
#define GEMM_GRID 391             // (N_NODES + 127) / 128

// ================= scratch (allocation-free: __device__ globals) =================
__device__ __half g_h16[N_NODES * D];
__device__ float g_rst[N_NODES * D];
__device__ int   g_cnt[N_NODES];
__device__ int   g_off[N_NODES + 1];
__device__ uint2 g_edge[E_MAX];
__device__ float g_sum1[D], g_sq1[D], g_sum2[D], g_sq2[D];
__device__ __align__(16) unsigned char g_B1img[2][TILE_BYTES];
__device__ __align__(16) unsigned char g_B2img[4][TILE_BYTES];
__device__ __align__(16) unsigned char g_featimg[2][PADROWS * TROW];
__device__ __align__(16) unsigned char g_aggimg[2][PADROWS * TROW];

// ================= warp-mma helpers =================
__device__ __forceinline__ uint32_t smem_u32(const void* p) {
    uint32_t a;
    asm("{ .reg .u64 t; cvta.to.shared.u64 t, %1; cvt.u32.u64 %0, t; }" : "=r"(a) : "l"(p));
    return a;
}
__device__ __forceinline__ void ldsm_x4(uint32_t* r, uint32_t addr) {
    asm volatile("ldmatrix.sync.aligned.m8n8.x4.shared.b16 {%0,%1,%2,%3}, [%4];"
                 : "=r"(r[0]), "=r"(r[1]), "=r"(r[2]), "=r"(r[3]) : "r"(addr));
}
__device__ __forceinline__ void mma_f16(float* d, const uint32_t* a, const uint32_t* b) {
    asm volatile(
        "mma.sync.aligned.m16n8k16.row.col.f32.f16.f16.f32 "
        "{%0,%1,%2,%3}, {%4,%5,%6,%7}, {%8,%9}, {%0,%1,%2,%3};"
        : "+f"(d[0]), "+f"(d[1]), "+f"(d[2]), "+f"(d[3])
        : "r"(a[0]), "r"(a[1]), "r"(a[2]), "r"(a[3]), "r"(b[0]), "r"(b[1]));
}

// ================= shared GEMM body (used by fusedB phase0 and hmma2) =================
template <int PHASE>
__device__ __forceinline__ void gemm_body(char* smem, uint32_t sbase, int blk,
                                          const float* __restrict__ bias) {
    const int tid = threadIdx.x;
    const int wid = tid >> 5;
    const int lane = tid & 31;
    const int r0 = blk * 128;
    const int NC = (PHASE == 0) ? 2 : 4;

    if (tid < 128) *(float*)(smem + tid * 4) = bias[tid];  // bias at smem[0..512)

    const int warp_m = wid & 3;
    const int warp_n = wid >> 2;
    const uint32_t a_off = (uint32_t)((warp_m * 32 + (lane & 15)) * TROW + (lane >> 4) * 16);
    const uint32_t b_off = (uint32_t)((warp_n * 64 + (lane & 7) + ((lane >> 4) << 3)) * TROW
                                      + ((lane >> 3) & 1) * 16);
    const int SM_A = 1024;
    const int SM_B = 1024 + TILE_BYTES;

    float acc[2][8][4];
#pragma unroll
    for (int mt = 0; mt < 2; mt++)
#pragma unroll
        for (int nt = 0; nt < 8; nt++)
#pragma unroll
            for (int q = 0; q < 4; q++) acc[mt][nt][q] = 0.f;

    for (int c = 0; c < NC; c++) {
        const unsigned char* imgA;
        if (PHASE == 0) imgA = g_featimg[c];
        else            imgA = (c < 2) ? g_featimg[c] : g_aggimg[c - 2];
        {
            const float4* asrc = (const float4*)(imgA + (size_t)r0 * TROW);
            const float4* bsrc = (PHASE == 0) ? (const float4*)g_B1img[c]
                                              : (const float4*)g_B2img[c];
            float4* adst = (float4*)(smem + SM_A);
            float4* bdst = (float4*)(smem + SM_B);
            const int nf4 = TILE_BYTES / 16;   // 1152
            for (int j = tid; j < nf4; j += 256) {
                adst[j] = asrc[j];
                bdst[j] = bsrc[j];
            }
        }
        __syncthreads();

#pragma unroll
        for (int ks = 0; ks < 4; ks++) {
            uint32_t a[2][4];
#pragma unroll
            for (int mt = 0; mt < 2; mt++)
                ldsm_x4(a[mt], sbase + SM_A + a_off + mt * (16 * TROW) + ks * 32);
            uint32_t b[4][4];
#pragma unroll
            for (int ng = 0; ng < 4; ng++)
                ldsm_x4(b[ng], sbase + SM_B + b_off + ng * (16 * TROW) + ks * 32);
#pragma unroll
            for (int mt = 0; mt < 2; mt++)
#pragma unroll
                for (int ng = 0; ng < 4; ng++) {
                    mma_f16(acc[mt][ng * 2 + 0], a[mt], &b[ng][0]);
                    mma_f16(acc[mt][ng * 2 + 1], a[mt], &b[ng][2]);
                }
        }
        __syncthreads();
    }

    const int er = r0 + warp_m * 32 + (lane >> 2);
    const int ec = warp_n * 64 + (lane & 3) * 2;
#pragma unroll
    for (int mt = 0; mt < 2; mt++) {
#pragma unroll
        for (int nt = 0; nt < 8; nt++) {
            int col = ec + nt * 8;
            float bx = *(float*)(smem + col * 4);
            float by = *(float*)(smem + (col + 1) * 4);
#pragma unroll
            for (int half = 0; half < 2; half++) {
                int row = er + mt * 16 + half * 8;
                if (row < N_NODES) {
                    float x = fmaxf(acc[mt][nt][half * 2 + 0] + bx, 0.f);
                    float y = fmaxf(acc[mt][nt][half * 2 + 1] + by, 0.f);
                    if (PHASE == 0) {
                        *(__half2*)(g_h16 + (size_t)row * 128 + col) = __floats2half2_rn(x, y);
                    } else {
                        float2 v; v.x = x; v.y = y;
                        *(float2*)(g_rst + (size_t)row * 128 + col) = v;
                    }
                }
            }
        }
    }
}

#define SM_TOTAL (1024 + 2 * TILE_BYTES)   // 37888

// ================= zero per-replay accumulators =================
__global__ void zero_kernel() {
    int idx = blockIdx.x * blockDim.x + threadIdx.x;
    int tot = blockDim.x * gridDim.x;
    for (int i = idx; i < N_NODES; i += tot) g_cnt[i] = 0;
    if (idx < D) { g_sum1[idx] = 0.f; g_sq1[idx] = 0.f; g_sum2[idx] = 0.f; g_sq2[idx] = 0.f; }
}

// ================= fusedA: hist | conv_feat | prep_B (block-partitioned) =================
__global__ __launch_bounds__(256) void fusedA(const int* __restrict__ dst, int E,
                                              const float* __restrict__ feat,
                                              const float* __restrict__ Qw,
                                              const float* __restrict__ Ww) {
    const int e_grid = (E + 255) >> 8;
    const int b = blockIdx.x;
    const int tid = threadIdx.x;
    if (b < e_grid) {
        // ---- hist ----
        int i = b * 256 + tid;
        if (i < E) atomicAdd(&g_cnt[dst[i]], 1);
    } else if (b < e_grid + 6250) {
        // ---- conv_feat: fp32 -> fp16 image ----
        int idx = (b - e_grid) * 256 + tid;
        if (idx >= N_NODES * 32) return;
        int node = idx >> 5, lane = idx & 31;
        float4 v = ((const float4*)feat)[(size_t)node * 32 + lane];
        __half2 p0 = __floats2half2_rn(v.x, v.y);
        __half2 p1 = __floats2half2_rn(v.z, v.w);
        int chunk = lane >> 4;
        int cin = (lane * 4) & 63;
        *(uint2*)(&g_featimg[chunk][(size_t)node * TROW + cin * 2]) =
            make_uint2(*(uint32_t*)&p0, *(uint32_t*)&p1);
    } else {
        // ---- prep_B (192 blocks x 256 = 49152 = 16384 + 32768) ----
        int idx = (b - e_grid - 6250) * 256 + tid;
        if (idx < 16384) {
            int r = idx >> 7, k = idx & 127;
            int chunk = k >> 6, kk = k & 63;
            *(__half*)(&g_B1img[chunk][(uint32_t)(r * TROW + kk * 2)]) =
                __float2half_rn(Qw[r * 128 + k]);
        } else {
            int e = idx - 16384;
            int r = e >> 8, k = e & 255;
            int chunk = k >> 6, kk = k & 63;
            *(__half*)(&g_B2img[chunk][(uint32_t)(r * TROW + kk * 2)]) =
                __float2half_rn(Ww[r * 256 + k]);
        }
    }
}

// ================= prefix scan (single block) =================
__global__ __launch_bounds__(1024) void prefix_kernel() {
    __shared__ int wsum[32];
    __shared__ int carry;
    int tid = threadIdx.x, lane = tid & 31, wid = tid >> 5;
    if (tid == 0) { carry = 0; g_off[0] = 0; }
    __syncthreads();
    for (int base = 0; base < N_NODES; base += 4096) {
        int i0 = base + tid * 4;
        int v[4];
#pragma unroll
        for (int j = 0; j < 4; j++) v[j] = (i0 + j < N_NODES) ? g_cnt[i0 + j] : 0;
        int local = v[0] + v[1] + v[2] + v[3];
        int x = local;
#pragma unroll
        for (int o = 1; o < 32; o <<= 1) {
            int y = __shfl_up_sync(0xFFFFFFFFu, x, o);
            if (lane >= o) x += y;
        }
        if (lane == 31) wsum[wid] = x;
        __syncthreads();
        if (wid == 0) {
            int s = wsum[lane];
#pragma unroll
            for (int o = 1; o < 32; o <<= 1) {
                int y = __shfl_up_sync(0xFFFFFFFFu, s, o);
                if (lane >= o) s += y;
            }
            wsum[lane] = s;
        }
        __syncthreads();
        int wbase = (wid == 0) ? 0 : wsum[wid - 1];
        int run = carry + wbase + x - local;
#pragma unroll
        for (int j = 0; j < 4; j++) {
            int i = i0 + j;
            if (i < N_NODES) {
                g_cnt[i] = run;
                g_off[i + 1] = run + v[j];
            }
            run += v[j];
        }
        __syncthreads();
        if (tid == 0) carry += wsum[31];
        __syncthreads();
    }
}

// ================= fusedB: GEMM1 (blocks [0,391)) | scatter (rest) =================
__global__ __launch_bounds__(256) void fusedB(const float* __restrict__ Qb,
                                              const float* __restrict__ w,
                                              const int* __restrict__ src,
                                              const int* __restrict__ dst, int E) {
    extern __shared__ char smem[];
    if (blockIdx.x < GEMM_GRID) {
        gemm_body<0>(smem, smem_u32(smem), blockIdx.x, Qb);
    } else {
        int i = (blockIdx.x - GEMM_GRID) * 256 + threadIdx.x;
        if (i >= E) return;
        int d = dst[i];
        int pos = atomicAdd(&g_cnt[d], 1);
        g_edge[pos] = make_uint2((uint32_t)src[i], __float_as_uint(w[i]));
    }
}

// ================= GEMM2 standalone =================
__global__ __launch_bounds__(256) void hmma2(const float* __restrict__ Wb) {
    extern __shared__ char smem[];
    gemm_body<1>(smem, smem_u32(smem), blockIdx.x, Wb);
}

// ================= column stats (phase 0: fp16 input) =================
__global__ void stats16_kernel() {
    __shared__ float s_s[128], s_q[128];
    int tid = threadIdx.x;
    if (tid < 128) { s_s[tid] = 0.f; s_q[tid] = 0.f; }
    __syncthreads();
    int lane = tid & 31;
    int wg = (blockIdx.x * blockDim.x + tid) >> 5;
    int wt = (gridDim.x * blockDim.x) >> 5;
    float4 s = make_float4(0.f, 0.f, 0.f, 0.f);
    float4 q = make_float4(0.f, 0.f, 0.f, 0.f);
    for (int r = wg; r < N_NODES; r += wt) {
        uint2 hp = ((const uint2*)(g_h16 + (size_t)r * 128))[lane];
        float2 f0 = __half22float2(*(const __half2*)&hp.x);
        float2 f1 = __half22float2(*(const __half2*)&hp.y);
        s.x += f0.x; s.y += f0.y; s.z += f1.x; s.w += f1.y;
        q.x += f0.x * f0.x; q.y += f0.y * f0.y;
        q.z += f1.x * f1.x; q.w += f1.y * f1.y;
    }
    atomicAdd(&s_s[lane * 4 + 0], s.x); atomicAdd(&s_s[lane * 4 + 1], s.y);
    atomicAdd(&s_s[lane * 4 + 2], s.z); atomicAdd(&s_s[lane * 4 + 3], s.w);
    atomicAdd(&s_q[lane * 4 + 0], q.x); atomicAdd(&s_q[lane * 4 + 1], q.y);
    atomicAdd(&s_q[lane * 4 + 2], q.z); atomicAdd(&s_q[lane * 4 + 3], q.w);
    __syncthreads();
    if (tid < 128) {
        atomicAdd(&g_sum1[tid], s_s[tid]);
        atomicAdd(&g_sq1[tid], s_q[tid]);
    }
}

// ================= column stats (phase 1: fp32 g_rst) =================
__global__ void stats32_kernel() {
    __shared__ float s_s[128], s_q[128];
    int tid = threadIdx.x;
    if (tid < 128) { s_s[tid] = 0.f; s_q[tid] = 0.f; }
    __syncthreads();
    int lane = tid & 31;
    int wg = (blockIdx.x * blockDim.x + tid) >> 5;
    int wt = (gridDim.x * blockDim.x) >> 5;
    float4 s = make_float4(0.f, 0.f, 0.f, 0.f);
    float4 q = make_float4(0.f, 0.f, 0.f, 0.f);
    for (int r = wg; r < N_NODES; r += wt) {
        float4 v = ((const float4*)g_rst)[(size_t)r * 32 + lane];
        s.x += v.x; s.y += v.y; s.z += v.z; s.w += v.w;
        q.x += v.x * v.x; q.y += v.y * v.y; q.z += v.z * v.z; q.w += v.w * v.w;
    }
    atomicAdd(&s_s[lane * 4 + 0], s.x); atomicAdd(&s_s[lane * 4 + 1], s.y);
    atomicAdd(&s_s[lane * 4 + 2], s.z); atomicAdd(&s_s[lane * 4 + 3], s.w);
    atomicAdd(&s_q[lane * 4 + 0], q.x); atomicAdd(&s_q[lane * 4 + 1], q.y);
    atomicAdd(&s_q[lane * 4 + 2], q.z); atomicAdd(&s_q[lane * 4 + 3], q.w);
    __syncthreads();
    if (tid < 128) {
        atomicAdd(&g_sum2[tid], s_s[tid]);
        atomicAdd(&g_sq2[tid], s_q[tid]);
    }
}

// ================= gather + per-block BN1 params + fold -> fp16 agg image =================
__global__ void gather_kernel(const float* __restrict__ gamma, const float* __restrict__ beta) {
    __shared__ __align__(16) float s_a[128];
    __shared__ __align__(16) float s_b[128];
    int tid = threadIdx.x;
    if (tid < 128) {
        float mean = g_sum1[tid] * (1.f / N_NODES);
        float var = g_sq1[tid] * (1.f / N_NODES) - mean * mean;
        float av = gamma[tid] * rsqrtf(var + EPS);
        s_a[tid] = av;
        s_b[tid] = beta[tid] - mean * av;
    }
    __syncthreads();

    int gw = (blockIdx.x * blockDim.x + tid) >> 5;
    int lane = tid & 31;
    if (gw >= N_NODES) return;
    int beg = g_off[gw], end = g_off[gw + 1];
    float a0 = 0.f, a1v = 0.f, a2v = 0.f, a3v = 0.f;
    float den = 0.f;
    int j = beg;
    for (; j + 1 < end; j += 2) {
        uint2 e0 = g_edge[j];
        uint2 e1 = g_edge[j + 1];
        uint2 hp0 = ((const uint2*)(g_h16 + (size_t)e0.x * 128))[lane];
        uint2 hp1 = ((const uint2*)(g_h16 + (size_t)e1.x * 128))[lane];
        float w0 = __uint_as_float(e0.y);
        float w1 = __uint_as_float(e1.y);
        float2 f0 = __half22float2(*(const __half2*)&hp0.x);
        float2 f1 = __half22float2(*(const __half2*)&hp0.y);
        float2 g0 = __half22float2(*(const __half2*)&hp1.x);
        float2 g1 = __half22float2(*(const __half2*)&hp1.y);
        a0 += w0 * f0.x + w1 * g0.x;
        a1v += w0 * f0.y + w1 * g0.y;
        a2v += w0 * f1.x + w1 * g1.x;
        a3v += w0 * f1.y + w1 * g1.y;
        den += w0 + w1;
    }
    if (j < end) {
        uint2 e = g_edge[j];
        float we = __uint_as_float(e.y);
        uint2 hp = ((const uint2*)(g_h16 + (size_t)e.x * 128))[lane];
        float2 f0 = __half22float2(*(const __half2*)&hp.x);
        float2 f1 = __half22float2(*(const __half2*)&hp.y);
        a0 += we * f0.x; a1v += we * f0.y;
        a2v += we * f1.x; a3v += we * f1.y;
        den += we;
    }
    float4 a = *(const float4*)&s_a[lane * 4];
    float4 b = *(const float4*)&s_b[lane * 4];
    float4 v;
    if (den != 0.f) {
        float inv = 1.f / den;
        v.x = a.x * (a0 * inv) + b.x;
        v.y = a.y * (a1v * inv) + b.y;
        v.z = a.z * (a2v * inv) + b.z;
        v.w = a.w * (a3v * inv) + b.w;
    } else {
        uint2 hp = ((const uint2*)(g_h16 + (size_t)gw * 128))[lane];
        float2 f0 = __half22float2(*(const __half2*)&hp.x);
        float2 f1 = __half22float2(*(const __half2*)&hp.y);
        v.x = a.x * f0.x + b.x;
        v.y = a.y * f0.y + b.y;
        v.z = a.z * f1.x + b.z;
        v.w = a.w * f1.y + b.w;
    }
    __half2 p0 = __floats2half2_rn(v.x, v.y);
    __half2 p1 = __floats2half2_rn(v.z, v.w);
    int chunk = lane >> 4;
    int cin = (lane * 4) & 63;
    *(uint2*)(&g_aggimg[chunk][(size_t)gw * TROW + cin * 2]) =
        make_uint2(*(uint32_t*)&p0, *(uint32_t*)&p1);
}

// ================= final: per-block BN2 params + BN2 + L2 normalize =================
__global__ void final_kernel(float* __restrict__ out, const float* __restrict__ gamma,
                             const float* __restrict__ beta) {
    __shared__ __align__(16) float s_a[128];
    __shared__ __align__(16) float s_b[128];
    int tid = threadIdx.x;
    if (tid < 128) {
        float mean = g_sum2[tid] * (1.f / N_NODES);
        float var = g_sq2[tid] * (1.f / N_NODES) - mean * mean;
        float av = gamma[tid] * rsqrtf(var + EPS);
        s_a[tid] = av;
        s_b[tid] = beta[tid] - mean * av;
    }
    __syncthreads();

    int gw = (blockIdx.x * blockDim.x + tid) >> 5;
    int lane = tid & 31;
    if (gw >= N_NODES) return;
    float4 a = *(const float4*)&s_a[lane * 4];
    float4 b = *(const float4*)&s_b[lane * 4];
    float4 v = ((const float4*)g_rst)[(size_t)gw * 32 + lane];
    v.x = v.x * a.x + b.x; v.y = v.y * a.y + b.y;
    v.z = v.z * a.z + b.z; v.w = v.w * a.w + b.w;
    float ss = v.x * v.x + v.y * v.y + v.z * v.z + v.w * v.w;
#pragma unroll
    for (int o = 16; o > 0; o >>= 1) ss += __shfl_xor_sync(0xFFFFFFFFu, ss, o);
    float norm = sqrtf(ss);
    float inv = (norm == 0.f) ? 1.f : 1.f / norm;
    v.x *= inv; v.y *= inv; v.z *= inv; v.w *= inv;
    ((float4*)out)[(size_t)gw * 32 + lane] = v;
}

extern "C" void kernel_launch(void* const* d_in, const int* in_sizes, int n_in,
                              void* d_out, int out_size) {
    const float* feat  = (const float*)d_in[0];
    const float* w     = (const float*)d_in[1];
    const float* Qw    = (const float*)d_in[2];
    const float* Qb    = (const float*)d_in[3];
    const float* Ww    = (const float*)d_in[4];
    const float* Wb    = (const float*)d_in[5];
    const float* gamma = (const float*)d_in[6];
    const float* beta  = (const float*)d_in[7];
    const int* src     = (const int*)d_in[8];
    const int* dst     = (const int*)d_in[9];
    const int E = in_sizes[1];
    float* out = (float*)d_out;

    static int smem_set = 0;
    if (!smem_set) {
        cudaFuncSetAttribute(fusedB, cudaFuncAttributeMaxDynamicSharedMemorySize, SM_TOTAL);
        cudaFuncSetAttribute(hmma2, cudaFuncAttributeMaxDynamicSharedMemorySize, SM_TOTAL);
        smem_set = 1;
    }

    const int warp_grid = (N_NODES * 32 + 255) / 256;   // 6250
    const int e_grid = (E + 255) / 256;                 // 3125

    zero_kernel<<<128, 256>>>();
    fusedA<<<e_grid + 6250 + 192, 256>>>(dst, E, feat, Qw, Ww);
    prefix_kernel<<<1, 1024>>>();
    fusedB<<<GEMM_GRID + e_grid, 256, SM_TOTAL>>>(Qb, w, src, dst, E);
    stats16_kernel<<<128, 256>>>();
    gather_kernel<<<warp_grid, 256>>>(gamma, beta);
    hmma2<<<GEMM_GRID, 256, SM_TOTAL>>>(Wb);
    stats32_kernel<<<128, 256>>>();
    final_kernel<<<warp_grid, 256>>>(out, gamma, beta);
}

// round 15
// speedup vs baseline: 1.3833x; 1.3833x over previous
#include <cuda_runtime.h>
#include <cuda_fp16.h>
#include <math.h>
#include <stdint.h>

#define N_NODES 50000
#define D 128
#define EPS 1e-5f
#define E_MAX 800000

// padded fp16 tile: rows x 64 cols, row stride 72 elems (144B = 9*16B -> bank rotate)
#define TROW 144
#define TILE_BYTES (128 * TROW)   // 18432
#define PADROWS 50048             // 391 tiles * 128

// ================= scratch (allocation-free: __device__ globals) =================
__device__ __half g_h16[N_NODES * D];
__device__ float g_rst[N_NODES * D];
__device__ int   g_cnt[N_NODES];
__device__ int   g_off[N_NODES + 1];
__device__ uint2 g_edge[E_MAX];
__device__ float g_sum1[D], g_sq1[D], g_sum2[D], g_sq2[D];
__device__ __align__(16) unsigned char g_B1img[2][TILE_BYTES];
__device__ __align__(16) unsigned char g_B2img[4][TILE_BYTES];
__device__ __align__(16) unsigned char g_featimg[2][PADROWS * TROW];
__device__ __align__(16) unsigned char g_aggimg[2][PADROWS * TROW];

// ================= warp-mma helpers =================
__device__ __forceinline__ uint32_t smem_u32(const void* p) {
    uint32_t a;
    asm("{ .reg .u64 t; cvta.to.shared.u64 t, %1; cvt.u32.u64 %0, t; }" : "=r"(a) : "l"(p));
    return a;
}
__device__ __forceinline__ void ldsm_x4(uint32_t* r, uint32_t addr) {
    asm volatile("ldmatrix.sync.aligned.m8n8.x4.shared.b16 {%0,%1,%2,%3}, [%4];"
                 : "=r"(r[0]), "=r"(r[1]), "=r"(r[2]), "=r"(r[3]) : "r"(addr));
}
__device__ __forceinline__ void mma_f16(float* d, const uint32_t* a, const uint32_t* b) {
    asm volatile(
        "mma.sync.aligned.m16n8k16.row.col.f32.f16.f16.f32 "
        "{%0,%1,%2,%3}, {%4,%5,%6,%7}, {%8,%9}, {%0,%1,%2,%3};"
        : "+f"(d[0]), "+f"(d[1]), "+f"(d[2]), "+f"(d[3])
        : "r"(a[0]), "r"(a[1]), "r"(a[2]), "r"(a[3]), "r"(b[0]), "r"(b[1]));
}

// ================= prep: zero accumulators | feat->fp16 image | weights->fp16 images =================
// All elementwise, no atomics, no smem: one launch, uniform low resource class.
__global__ __launch_bounds__(256) void prep_kernel(const float* __restrict__ feat,
                                                   const float* __restrict__ Qw,
                                                   const float* __restrict__ Ww,
                                                   int E_unused) {
    const int b = blockIdx.x;
    const int tid = threadIdx.x;
    if (b < 6250) {
        // conv_feat: fp32 -> fp16 image
        int idx = b * 256 + tid;
        if (idx >= N_NODES * 32) return;
        int node = idx >> 5, lane = idx & 31;
        float4 v = ((const float4*)feat)[(size_t)node * 32 + lane];
        __half2 p0 = __floats2half2_rn(v.x, v.y);
        __half2 p1 = __floats2half2_rn(v.z, v.w);
        int chunk = lane >> 4;
        int cin = (lane * 4) & 63;
        *(uint2*)(&g_featimg[chunk][(size_t)node * TROW + cin * 2]) =
            make_uint2(*(uint32_t*)&p0, *(uint32_t*)&p1);
    } else if (b < 6250 + 192) {
        // prep_B
        int idx = (b - 6250) * 256 + tid;
        if (idx < 16384) {
            int r = idx >> 7, k = idx & 127;
            int chunk = k >> 6, kk = k & 63;
            *(__half*)(&g_B1img[chunk][(uint32_t)(r * TROW + kk * 2)]) =
                __float2half_rn(Qw[r * 128 + k]);
        } else {
            int e = idx - 16384;
            int r = e >> 8, k = e & 255;
            int chunk = k >> 6, kk = k & 63;
            *(__half*)(&g_B2img[chunk][(uint32_t)(r * TROW + kk * 2)]) =
                __float2half_rn(Ww[r * 256 + k]);
        }
    } else {
        // zero g_cnt + stats accumulators (196 blocks x 256 >= 50000)
        int idx = (b - 6250 - 192) * 256 + tid;
        if (idx < N_NODES) g_cnt[idx] = 0;
        if (idx < D) { g_sum1[idx] = 0.f; g_sq1[idx] = 0.f; g_sum2[idx] = 0.f; g_sq2[idx] = 0.f; }
    }
}

// ================= HMMA GEMM (fp16, pure-copy fills): C = relu(A @ B^T + bias) =================
#define SM_BIAS 0
#define SM_A    1024
#define SM_B    (1024 + TILE_BYTES)
#define SM_TOTAL (1024 + 2 * TILE_BYTES)   // 37888

template <int PHASE>
__global__ __launch_bounds__(256) void hmma_gemm(const float* __restrict__ bias) {
    extern __shared__ char smem[];
    const uint32_t sbase = smem_u32(smem);
    const int tid = threadIdx.x;
    const int wid = tid >> 5;
    const int lane = tid & 31;
    const int r0 = blockIdx.x * 128;
    const int NC = (PHASE == 0) ? 2 : 4;

    if (tid < 128) *(float*)(smem + SM_BIAS + tid * 4) = bias[tid];

    const int warp_m = wid & 3;
    const int warp_n = wid >> 2;
    const uint32_t a_off = (uint32_t)((warp_m * 32 + (lane & 15)) * TROW + (lane >> 4) * 16);
    const uint32_t b_off = (uint32_t)((warp_n * 64 + (lane & 7) + ((lane >> 4) << 3)) * TROW
                                      + ((lane >> 3) & 1) * 16);

    float acc[2][8][4];
#pragma unroll
    for (int mt = 0; mt < 2; mt++)
#pragma unroll
        for (int nt = 0; nt < 8; nt++)
#pragma unroll
            for (int q = 0; q < 4; q++) acc[mt][nt][q] = 0.f;

    for (int c = 0; c < NC; c++) {
        const unsigned char* imgA;
        if (PHASE == 0) imgA = g_featimg[c];
        else            imgA = (c < 2) ? g_featimg[c] : g_aggimg[c - 2];
        {
            const float4* asrc = (const float4*)(imgA + (size_t)r0 * TROW);
            const float4* bsrc = (PHASE == 0) ? (const float4*)g_B1img[c]
                                              : (const float4*)g_B2img[c];
            float4* adst = (float4*)(smem + SM_A);
            float4* bdst = (float4*)(smem + SM_B);
            const int nf4 = TILE_BYTES / 16;   // 1152
            for (int j = tid; j < nf4; j += 256) {
                adst[j] = asrc[j];
                bdst[j] = bsrc[j];
            }
        }
        __syncthreads();

#pragma unroll
        for (int ks = 0; ks < 4; ks++) {
            uint32_t a[2][4];
#pragma unroll
            for (int mt = 0; mt < 2; mt++)
                ldsm_x4(a[mt], sbase + SM_A + a_off + mt * (16 * TROW) + ks * 32);
            uint32_t b[4][4];
#pragma unroll
            for (int ng = 0; ng < 4; ng++)
                ldsm_x4(b[ng], sbase + SM_B + b_off + ng * (16 * TROW) + ks * 32);
#pragma unroll
            for (int mt = 0; mt < 2; mt++)
#pragma unroll
                for (int ng = 0; ng < 4; ng++) {
                    mma_f16(acc[mt][ng * 2 + 0], a[mt], &b[ng][0]);
                    mma_f16(acc[mt][ng * 2 + 1], a[mt], &b[ng][2]);
                }
        }
        __syncthreads();
    }

    const int er = r0 + warp_m * 32 + (lane >> 2);
    const int ec = warp_n * 64 + (lane & 3) * 2;
#pragma unroll
    for (int mt = 0; mt < 2; mt++) {
#pragma unroll
        for (int nt = 0; nt < 8; nt++) {
            int col = ec + nt * 8;
            float bx = *(float*)(smem + SM_BIAS + col * 4);
            float by = *(float*)(smem + SM_BIAS + (col + 1) * 4);
#pragma unroll
            for (int half = 0; half < 2; half++) {
                int row = er + mt * 16 + half * 8;
                if (row < N_NODES) {
                    float x = fmaxf(acc[mt][nt][half * 2 + 0] + bx, 0.f);
                    float y = fmaxf(acc[mt][nt][half * 2 + 1] + by, 0.f);
                    if (PHASE == 0) {
                        *(__half2*)(g_h16 + (size_t)row * 128 + col) = __floats2half2_rn(x, y);
                    } else {
                        float2 v; v.x = x; v.y = y;
                        *(float2*)(g_rst + (size_t)row * 128 + col) = v;
                    }
                }
            }
        }
    }
}

// ================= column stats (phase 0: fp16 input) =================
__global__ void stats16_kernel() {
    __shared__ float s_s[128], s_q[128];
    int tid = threadIdx.x;
    if (tid < 128) { s_s[tid] = 0.f; s_q[tid] = 0.f; }
    __syncthreads();
    int lane = tid & 31;
    int wg = (blockIdx.x * blockDim.x + tid) >> 5;
    int wt = (gridDim.x * blockDim.x) >> 5;
    float4 s = make_float4(0.f, 0.f, 0.f, 0.f);
    float4 q = make_float4(0.f, 0.f, 0.f, 0.f);
    for (int r = wg; r < N_NODES; r += wt) {
        uint2 hp = ((const uint2*)(g_h16 + (size_t)r * 128))[lane];
        float2 f0 = __half22float2(*(const __half2*)&hp.x);
        float2 f1 = __half22float2(*(const __half2*)&hp.y);
        s.x += f0.x; s.y += f0.y; s.z += f1.x; s.w += f1.y;
        q.x += f0.x * f0.x; q.y += f0.y * f0.y;
        q.z += f1.x * f1.x; q.w += f1.y * f1.y;
    }
    atomicAdd(&s_s[lane * 4 + 0], s.x); atomicAdd(&s_s[lane * 4 + 1], s.y);
    atomicAdd(&s_s[lane * 4 + 2], s.z); atomicAdd(&s_s[lane * 4 + 3], s.w);
    atomicAdd(&s_q[lane * 4 + 0], q.x); atomicAdd(&s_q[lane * 4 + 1], q.y);
    atomicAdd(&s_q[lane * 4 + 2], q.z); atomicAdd(&s_q[lane * 4 + 3], q.w);
    __syncthreads();
    if (tid < 128) {
        atomicAdd(&g_sum1[tid], s_s[tid]);
        atomicAdd(&g_sq1[tid], s_q[tid]);
    }
}

// ================= column stats (phase 1: fp32 g_rst) =================
__global__ void stats32_kernel() {
    __shared__ float s_s[128], s_q[128];
    int tid = threadIdx.x;
    if (tid < 128) { s_s[tid] = 0.f; s_q[tid] = 0.f; }
    __syncthreads();
    int lane = tid & 31;
    int wg = (blockIdx.x * blockDim.x + tid) >> 5;
    int wt = (gridDim.x * blockDim.x) >> 5;
    float4 s = make_float4(0.f, 0.f, 0.f, 0.f);
    float4 q = make_float4(0.f, 0.f, 0.f, 0.f);
    for (int r = wg; r < N_NODES; r += wt) {
        float4 v = ((const float4*)g_rst)[(size_t)r * 32 + lane];
        s.x += v.x; s.y += v.y; s.z += v.z; s.w += v.w;
        q.x += v.x * v.x; q.y += v.y * v.y; q.z += v.z * v.z; q.w += v.w * v.w;
    }
    atomicAdd(&s_s[lane * 4 + 0], s.x); atomicAdd(&s_s[lane * 4 + 1], s.y);
    atomicAdd(&s_s[lane * 4 + 2], s.z); atomicAdd(&s_s[lane * 4 + 3], s.w);
    atomicAdd(&s_q[lane * 4 + 0], q.x); atomicAdd(&s_q[lane * 4 + 1], q.y);
    atomicAdd(&s_q[lane * 4 + 2], q.z); atomicAdd(&s_q[lane * 4 + 3], q.w);
    __syncthreads();
    if (tid < 128) {
        atomicAdd(&g_sum2[tid], s_s[tid]);
        atomicAdd(&g_sq2[tid], s_q[tid]);
    }
}

// ================= CSR build =================
__global__ void hist_kernel(const int* __restrict__ dst, int E) {
    int i = blockIdx.x * blockDim.x + threadIdx.x;
    if (i < E) atomicAdd(&g_cnt[dst[i]], 1);
}

__global__ __launch_bounds__(1024) void prefix_kernel() {
    __shared__ int wsum[32];
    __shared__ int carry;
    int tid = threadIdx.x, lane = tid & 31, wid = tid >> 5;
    if (tid == 0) { carry = 0; g_off[0] = 0; }
    __syncthreads();
    for (int base = 0; base < N_NODES; base += 4096) {
        int i0 = base + tid * 4;
        int v[4];
#pragma unroll
        for (int j = 0; j < 4; j++) v[j] = (i0 + j < N_NODES) ? g_cnt[i0 + j] : 0;
        int local = v[0] + v[1] + v[2] + v[3];
        int x = local;
#pragma unroll
        for (int o = 1; o < 32; o <<= 1) {
            int y = __shfl_up_sync(0xFFFFFFFFu, x, o);
            if (lane >= o) x += y;
        }
        if (lane == 31) wsum[wid] = x;
        __syncthreads();
        if (wid == 0) {
            int s = wsum[lane];
#pragma unroll
            for (int o = 1; o < 32; o <<= 1) {
                int y = __shfl_up_sync(0xFFFFFFFFu, s, o);
                if (lane >= o) s += y;
            }
            wsum[lane] = s;
        }
        __syncthreads();
        int wbase = (wid == 0) ? 0 : wsum[wid - 1];
        int run = carry + wbase + x - local;
#pragma unroll
        for (int j = 0; j < 4; j++) {
            int i = i0 + j;
            if (i < N_NODES) {
                g_cnt[i] = run;
                g_off[i + 1] = run + v[j];
            }
            run += v[j];
        }
        __syncthreads();
        if (tid == 0) carry += wsum[31];
        __syncthreads();
    }
}

__global__ void scatter_kernel(const float* __restrict__ w, const int* __restrict__ src,
                               const int* __restrict__ dst, int E) {
    int i = blockIdx.x * blockDim.x + threadIdx.x;
    if (i >= E) return;
    int d = dst[i];
    int pos = atomicAdd(&g_cnt[d], 1);
    g_edge[pos] = make_uint2((uint32_t)src[i], __float_as_uint(w[i]));
}

// ================= gather (4x unroll) + per-block BN1 params + fold -> fp16 agg image =================
__global__ void gather_kernel(const float* __restrict__ gamma, const float* __restrict__ beta) {
    __shared__ __align__(16) float s_a[128];
    __shared__ __align__(16) float s_b[128];
    int tid = threadIdx.x;
    if (tid < 128) {
        float mean = g_sum1[tid] * (1.f / N_NODES);
        float var = g_sq1[tid] * (1.f / N_NODES) - mean * mean;
        float av = gamma[tid] * rsqrtf(var + EPS);
        s_a[tid] = av;
        s_b[tid] = beta[tid] - mean * av;
    }
    __syncthreads();

    int gw = (blockIdx.x * blockDim.x + tid) >> 5;
    int lane = tid & 31;
    if (gw >= N_NODES) return;
    int beg = g_off[gw], end = g_off[gw + 1];
    float a0 = 0.f, a1v = 0.f, a2v = 0.f, a3v = 0.f;
    float den = 0.f;
    int j = beg;
    // 4x unrolled main loop for MLP=4 outstanding L2 loads per lane
    for (; j + 3 < end; j += 4) {
        uint2 e0 = g_edge[j];
        uint2 e1 = g_edge[j + 1];
        uint2 e2 = g_edge[j + 2];
        uint2 e3 = g_edge[j + 3];
        uint2 h0 = ((const uint2*)(g_h16 + (size_t)e0.x * 128))[lane];
        uint2 h1 = ((const uint2*)(g_h16 + (size_t)e1.x * 128))[lane];
        uint2 h2 = ((const uint2*)(g_h16 + (size_t)e2.x * 128))[lane];
        uint2 h3 = ((const uint2*)(g_h16 + (size_t)e3.x * 128))[lane];
        float w0 = __uint_as_float(e0.y), w1 = __uint_as_float(e1.y);
        float w2 = __uint_as_float(e2.y), w3 = __uint_as_float(e3.y);
        float2 p00 = __half22float2(*(const __half2*)&h0.x);
        float2 p01 = __half22float2(*(const __half2*)&h0.y);
        float2 p10 = __half22float2(*(const __half2*)&h1.x);
        float2 p11 = __half22float2(*(const __half2*)&h1.y);
        float2 p20 = __half22float2(*(const __half2*)&h2.x);
        float2 p21 = __half22float2(*(const __half2*)&h2.y);
        float2 p30 = __half22float2(*(const __half2*)&h3.x);
        float2 p31 = __half22float2(*(const __half2*)&h3.y);
        a0  += w0 * p00.x + w1 * p10.x + w2 * p20.x + w3 * p30.x;
        a1v += w0 * p00.y + w1 * p10.y + w2 * p20.y + w3 * p30.y;
        a2v += w0 * p01.x + w1 * p11.x + w2 * p21.x + w3 * p31.x;
        a3v += w0 * p01.y + w1 * p11.y + w2 * p21.y + w3 * p31.y;
        den += w0 + w1 + w2 + w3;
    }
    for (; j < end; j++) {
        uint2 e = g_edge[j];
        float we = __uint_as_float(e.y);
        uint2 hp = ((const uint2*)(g_h16 + (size_t)e.x * 128))[lane];
        float2 f0 = __half22float2(*(const __half2*)&hp.x);
        float2 f1 = __half22float2(*(const __half2*)&hp.y);
        a0 += we * f0.x; a1v += we * f0.y;
        a2v += we * f1.x; a3v += we * f1.y;
        den += we;
    }
    float4 a = *(const float4*)&s_a[lane * 4];
    float4 b = *(const float4*)&s_b[lane * 4];
    float4 v;
    if (den != 0.f) {
        float inv = 1.f / den;
        v.x = a.x * (a0 * inv) + b.x;
        v.y = a.y * (a1v * inv) + b.y;
        v.z = a.z * (a2v * inv) + b.z;
        v.w = a.w * (a3v * inv) + b.w;
    } else {
        uint2 hp = ((const uint2*)(g_h16 + (size_t)gw * 128))[lane];
        float2 f0 = __half22float2(*(const __half2*)&hp.x);
        float2 f1 = __half22float2(*(const __half2*)&hp.y);
        v.x = a.x * f0.x + b.x;
        v.y = a.y * f0.y + b.y;
        v.z = a.z * f1.x + b.z;
        v.w = a.w * f1.y + b.w;
    }
    __half2 p0 = __floats2half2_rn(v.x, v.y);
    __half2 p1 = __floats2half2_rn(v.z, v.w);
    int chunk = lane >> 4;
    int cin = (lane * 4) & 63;
    *(uint2*)(&g_aggimg[chunk][(size_t)gw * TROW + cin * 2]) =
        make_uint2(*(uint32_t*)&p0, *(uint32_t*)&p1);
}

// ================= final: per-block BN2 params + BN2 + L2 normalize =================
__global__ void final_kernel(float* __restrict__ out, const float* __restrict__ gamma,
                             const float* __restrict__ beta) {
    __shared__ __align__(16) float s_a[128];
    __shared__ __align__(16) float s_b[128];
    int tid = threadIdx.x;
    if (tid < 128) {
        float mean = g_sum2[tid] * (1.f / N_NODES);
        float var = g_sq2[tid] * (1.f / N_NODES) - mean * mean;
        float av = gamma[tid] * rsqrtf(var + EPS);
        s_a[tid] = av;
        s_b[tid] = beta[tid] - mean * av;
    }
    __syncthreads();

    int gw = (blockIdx.x * blockDim.x + tid) >> 5;
    int lane = tid & 31;
    if (gw >= N_NODES) return;
    float4 a = *(const float4*)&s_a[lane * 4];
    float4 b = *(const float4*)&s_b[lane * 4];
    float4 v = ((const float4*)g_rst)[(size_t)gw * 32 + lane];
    v.x = v.x * a.x + b.x; v.y = v.y * a.y + b.y;
    v.z = v.z * a.z + b.z; v.w = v.w * a.w + b.w;
    float ss = v.x * v.x + v.y * v.y + v.z * v.z + v.w * v.w;
#pragma unroll
    for (int o = 16; o > 0; o >>= 1) ss += __shfl_xor_sync(0xFFFFFFFFu, ss, o);
    float norm = sqrtf(ss);
    float inv = (norm == 0.f) ? 1.f : 1.f / norm;
    v.x *= inv; v.y *= inv; v.z *= inv; v.w *= inv;
    ((float4*)out)[(size_t)gw * 32 + lane] = v;
}

extern "C" void kernel_launch(void* const* d_in, const int* in_sizes, int n_in,
                              void* d_out, int out_size) {
    const float* feat  = (const float*)d_in[0];
    const float* w     = (const float*)d_in[1];
    const float* Qw    = (const float*)d_in[2];
    const float* Qb    = (const float*)d_in[3];
    const float* Ww    = (const float*)d_in[4];
    const float* Wb    = (const float*)d_in[5];
    const float* gamma = (const float*)d_in[6];
    const float* beta  = (const float*)d_in[7];
    const int* src     = (const int*)d_in[8];
    const int* dst     = (const int*)d_in[9];
    const int E = in_sizes[1];
    float* out = (float*)d_out;

    static int smem_set = 0;
    if (!smem_set) {
        cudaFuncSetAttribute(hmma_gemm<0>, cudaFuncAttributeMaxDynamicSharedMemorySize, SM_TOTAL);
        cudaFuncSetAttribute(hmma_gemm<1>, cudaFuncAttributeMaxDynamicSharedMemorySize, SM_TOTAL);
        smem_set = 1;
    }

    const int tile_grid = (N_NODES + 127) / 128;        // 391
    const int warp_grid = (N_NODES * 32 + 255) / 256;   // 6250
    const int e_grid = (E + 255) / 256;                 // 3125

    prep_kernel<<<6250 + 192 + 196, 256>>>(feat, Qw, Ww, E);
    hist_kernel<<<e_grid, 256>>>(dst, E);
    prefix_kernel<<<1, 1024>>>();
    scatter_kernel<<<e_grid, 256>>>(w, src, dst, E);
    hmma_gemm<0><<<tile_grid, 256, SM_TOTAL>>>(Qb);
    stats16_kernel<<<128, 256>>>();
    gather_kernel<<<warp_grid, 256>>>(gamma, beta);
    hmma_gemm<1><<<tile_grid, 256, SM_TOTAL>>>(Wb);
    stats32_kernel<<<128, 256>>>();
    final_kernel<<<warp_grid, 256>>>(out, gamma, beta);
}

// round 17
// speedup vs baseline: 1.6029x; 1.1587x over previous
#include <cuda_runtime.h>
#include <cuda_fp16.h>
#include <math.h>
#include <stdint.h>

#define N_NODES 50000
#define D 128
#define EPS 1e-5f
#define E_MAX 800000

// padded fp16 tile: rows x 64 cols, row stride 72 elems (144B = 9*16B -> bank rotate)
#define TROW 144
#define TILE_BYTES (128 * TROW)   // 18432
#define PADROWS 50048             // 391 tiles * 128

// ================= scratch (allocation-free: __device__ globals) =================
__device__ __half g_h16[N_NODES * D];
__device__ __half g_rst16[N_NODES * D];      // fp16 GEMM2 output (stats+final only)
__device__ int   g_cnt[N_NODES];
__device__ int   g_off[N_NODES + 1];
__device__ uint2 g_edge[E_MAX];
__device__ float g_sum1[D], g_sq1[D], g_sum2[D], g_sq2[D];
__device__ __align__(16) unsigned char g_B1img[2][TILE_BYTES];
__device__ __align__(16) unsigned char g_B2img[4][TILE_BYTES];
__device__ __align__(16) unsigned char g_featimg[2][PADROWS * TROW];
__device__ __align__(16) unsigned char g_aggimg[2][PADROWS * TROW];

// ================= helpers =================
__device__ __forceinline__ uint32_t smem_u32(const void* p) {
    uint32_t a;
    asm("{ .reg .u64 t; cvta.to.shared.u64 t, %1; cvt.u32.u64 %0, t; }" : "=r"(a) : "l"(p));
    return a;
}
__device__ __forceinline__ void ldsm_x4(uint32_t* r, uint32_t addr) {
    asm volatile("ldmatrix.sync.aligned.m8n8.x4.shared.b16 {%0,%1,%2,%3}, [%4];"
                 : "=r"(r[0]), "=r"(r[1]), "=r"(r[2]), "=r"(r[3]) : "r"(addr));
}
__device__ __forceinline__ void mma_f16(float* d, const uint32_t* a, const uint32_t* b) {
    asm volatile(
        "mma.sync.aligned.m16n8k16.row.col.f32.f16.f16.f32 "
        "{%0,%1,%2,%3}, {%4,%5,%6,%7}, {%8,%9}, {%0,%1,%2,%3};"
        : "+f"(d[0]), "+f"(d[1]), "+f"(d[2]), "+f"(d[3])
        : "r"(a[0]), "r"(a[1]), "r"(a[2]), "r"(a[3]), "r"(b[0]), "r"(b[1]));
}
__device__ __forceinline__ void cp_async16(uint32_t saddr, const void* gaddr) {
    asm volatile("cp.async.cg.shared.global [%0], [%1], 16;" :: "r"(saddr), "l"(gaddr));
}

// ================= prep: feat->fp16 image | weights->fp16 images | zero =================
__global__ __launch_bounds__(256) void prep_kernel(const float* __restrict__ feat,
                                                   const float* __restrict__ Qw,
                                                   const float* __restrict__ Ww) {
    const int b = blockIdx.x;
    const int tid = threadIdx.x;
    if (b < 6250) {
        int idx = b * 256 + tid;
        if (idx >= N_NODES * 32) return;
        int node = idx >> 5, lane = idx & 31;
        float4 v = ((const float4*)feat)[(size_t)node * 32 + lane];
        __half2 p0 = __floats2half2_rn(v.x, v.y);
        __half2 p1 = __floats2half2_rn(v.z, v.w);
        int chunk = lane >> 4;
        int cin = (lane * 4) & 63;
        *(uint2*)(&g_featimg[chunk][(size_t)node * TROW + cin * 2]) =
            make_uint2(*(uint32_t*)&p0, *(uint32_t*)&p1);
    } else if (b < 6250 + 192) {
        int idx = (b - 6250) * 256 + tid;
        if (idx < 16384) {
            int r = idx >> 7, k = idx & 127;
            int chunk = k >> 6, kk = k & 63;
            *(__half*)(&g_B1img[chunk][(uint32_t)(r * TROW + kk * 2)]) =
                __float2half_rn(Qw[r * 128 + k]);
        } else {
            int e = idx - 16384;
            int r = e >> 8, k = e & 255;
            int chunk = k >> 6, kk = k & 63;
            *(__half*)(&g_B2img[chunk][(uint32_t)(r * TROW + kk * 2)]) =
                __float2half_rn(Ww[r * 256 + k]);
        }
    } else {
        int idx = (b - 6250 - 192) * 256 + tid;
        if (idx < N_NODES) g_cnt[idx] = 0;
        if (idx < D) { g_sum1[idx] = 0.f; g_sq1[idx] = 0.f; g_sum2[idx] = 0.f; g_sq2[idx] = 0.f; }
    }
}

// ================= HMMA GEMM: cp.async double-buffered K-pipeline =================
// smem: [0..512) bias, buffers at 1024: buf0{A,B}, buf1{A,B}
#define SM_TILES 1024
#define SM_TOTAL (1024 + 4 * TILE_BYTES)   // 74752

template <int PHASE>
__global__ __launch_bounds__(256) void hmma_gemm(const float* __restrict__ bias) {
    extern __shared__ char smem[];
    const uint32_t sbase = smem_u32(smem);
    const int tid = threadIdx.x;
    const int wid = tid >> 5;
    const int lane = tid & 31;
    const int r0 = blockIdx.x * 128;
    const int NC = (PHASE == 0) ? 2 : 4;

    if (tid < 128) *(float*)(smem + tid * 4) = bias[tid];

    const int warp_m = wid & 3;
    const int warp_n = wid >> 2;
    const uint32_t a_off = (uint32_t)((warp_m * 32 + (lane & 15)) * TROW + (lane >> 4) * 16);
    const uint32_t b_off = (uint32_t)((warp_n * 64 + (lane & 7) + ((lane >> 4) << 3)) * TROW
                                      + ((lane >> 3) & 1) * 16);

    float acc[2][8][4];
#pragma unroll
    for (int mt = 0; mt < 2; mt++)
#pragma unroll
        for (int nt = 0; nt < 8; nt++)
#pragma unroll
            for (int q = 0; q < 4; q++) acc[mt][nt][q] = 0.f;

    auto issue = [&](int c, int buf) {
        const unsigned char* imgA;
        if (PHASE == 0) imgA = g_featimg[c];
        else            imgA = (c < 2) ? g_featimg[c] : g_aggimg[c - 2];
        const float4* asrc = (const float4*)(imgA + (size_t)r0 * TROW);
        const float4* bsrc = (PHASE == 0) ? (const float4*)g_B1img[c]
                                          : (const float4*)g_B2img[c];
        uint32_t sa = sbase + SM_TILES + (uint32_t)buf * 2 * TILE_BYTES;
        uint32_t sb = sa + TILE_BYTES;
        const int nf4 = TILE_BYTES / 16;   // 1152
        for (int j = tid; j < nf4; j += 256) {
            cp_async16(sa + j * 16, asrc + j);
            cp_async16(sb + j * 16, bsrc + j);
        }
        asm volatile("cp.async.commit_group;" ::: "memory");
    };

    issue(0, 0);
    for (int c = 0; c < NC; c++) {
        if (c + 1 < NC) {
            issue(c + 1, (c + 1) & 1);
            asm volatile("cp.async.wait_group 1;" ::: "memory");
        } else {
            asm volatile("cp.async.wait_group 0;" ::: "memory");
        }
        __syncthreads();

        const uint32_t sa = sbase + SM_TILES + (uint32_t)(c & 1) * 2 * TILE_BYTES;
        const uint32_t sb = sa + TILE_BYTES;
#pragma unroll
        for (int ks = 0; ks < 4; ks++) {
            uint32_t a[2][4];
#pragma unroll
            for (int mt = 0; mt < 2; mt++)
                ldsm_x4(a[mt], sa + a_off + mt * (16 * TROW) + ks * 32);
            uint32_t b[4][4];
#pragma unroll
            for (int ng = 0; ng < 4; ng++)
                ldsm_x4(b[ng], sb + b_off + ng * (16 * TROW) + ks * 32);
#pragma unroll
            for (int mt = 0; mt < 2; mt++)
#pragma unroll
                for (int ng = 0; ng < 4; ng++) {
                    mma_f16(acc[mt][ng * 2 + 0], a[mt], &b[ng][0]);
                    mma_f16(acc[mt][ng * 2 + 1], a[mt], &b[ng][2]);
                }
        }
        __syncthreads();   // all warps done with buf (c&1) before it's re-issued
    }

    // ---- epilogue: bias + relu + fp16 store ----
    const int er = r0 + warp_m * 32 + (lane >> 2);
    const int ec = warp_n * 64 + (lane & 3) * 2;
    __half* Cout = (PHASE == 0) ? g_h16 : g_rst16;
#pragma unroll
    for (int mt = 0; mt < 2; mt++) {
#pragma unroll
        for (int nt = 0; nt < 8; nt++) {
            int col = ec + nt * 8;
            float bx = *(float*)(smem + col * 4);
            float by = *(float*)(smem + (col + 1) * 4);
#pragma unroll
            for (int half = 0; half < 2; half++) {
                int row = er + mt * 16 + half * 8;
                if (row < N_NODES) {
                    float x = fmaxf(acc[mt][nt][half * 2 + 0] + bx, 0.f);
                    float y = fmaxf(acc[mt][nt][half * 2 + 1] + by, 0.f);
                    *(__half2*)(Cout + (size_t)row * 128 + col) = __floats2half2_rn(x, y);
                }
            }
        }
    }
}

// ================= column stats (device-side symbol refs — no host symbol passing!) =================
template <int PHASE>
__global__ void stats_kernel() {
    __shared__ float s_s[128], s_q[128];
    const __half* X = (PHASE == 0) ? g_h16 : g_rst16;
    int tid = threadIdx.x;
    if (tid < 128) { s_s[tid] = 0.f; s_q[tid] = 0.f; }
    __syncthreads();
    int lane = tid & 31;
    int wg = (blockIdx.x * blockDim.x + tid) >> 5;
    int wt = (gridDim.x * blockDim.x) >> 5;
    float4 s = make_float4(0.f, 0.f, 0.f, 0.f);
    float4 q = make_float4(0.f, 0.f, 0.f, 0.f);
    for (int r = wg; r < N_NODES; r += wt) {
        uint2 hp = ((const uint2*)(X + (size_t)r * 128))[lane];
        float2 f0 = __half22float2(*(const __half2*)&hp.x);
        float2 f1 = __half22float2(*(const __half2*)&hp.y);
        s.x += f0.x; s.y += f0.y; s.z += f1.x; s.w += f1.y;
        q.x += f0.x * f0.x; q.y += f0.y * f0.y;
        q.z += f1.x * f1.x; q.w += f1.y * f1.y;
    }
    atomicAdd(&s_s[lane * 4 + 0], s.x); atomicAdd(&s_s[lane * 4 + 1], s.y);
    atomicAdd(&s_s[lane * 4 + 2], s.z); atomicAdd(&s_s[lane * 4 + 3], s.w);
    atomicAdd(&s_q[lane * 4 + 0], q.x); atomicAdd(&s_q[lane * 4 + 1], q.y);
    atomicAdd(&s_q[lane * 4 + 2], q.z); atomicAdd(&s_q[lane * 4 + 3], q.w);
    __syncthreads();
    if (tid < 128) {
        float* gs = (PHASE == 0) ? g_sum1 : g_sum2;
        float* gq = (PHASE == 0) ? g_sq1 : g_sq2;
        atomicAdd(&gs[tid], s_s[tid]);
        atomicAdd(&gq[tid], s_q[tid]);
    }
}

// ================= CSR build =================
__global__ void hist_kernel(const int* __restrict__ dst, int E) {
    int i = blockIdx.x * blockDim.x + threadIdx.x;
    if (i < E) atomicAdd(&g_cnt[dst[i]], 1);
}

__global__ __launch_bounds__(1024) void prefix_kernel() {
    __shared__ int wsum[32];
    __shared__ int carry;
    int tid = threadIdx.x, lane = tid & 31, wid = tid >> 5;
    if (tid == 0) { carry = 0; g_off[0] = 0; }
    __syncthreads();
    for (int base = 0; base < N_NODES; base += 4096) {
        int i0 = base + tid * 4;
        int v[4];
#pragma unroll
        for (int j = 0; j < 4; j++) v[j] = (i0 + j < N_NODES) ? g_cnt[i0 + j] : 0;
        int local = v[0] + v[1] + v[2] + v[3];
        int x = local;
#pragma unroll
        for (int o = 1; o < 32; o <<= 1) {
            int y = __shfl_up_sync(0xFFFFFFFFu, x, o);
            if (lane >= o) x += y;
        }
        if (lane == 31) wsum[wid] = x;
        __syncthreads();
        if (wid == 0) {
            int s = wsum[lane];
#pragma unroll
            for (int o = 1; o < 32; o <<= 1) {
                int y = __shfl_up_sync(0xFFFFFFFFu, s, o);
                if (lane >= o) s += y;
            }
            wsum[lane] = s;
        }
        __syncthreads();
        int wbase = (wid == 0) ? 0 : wsum[wid - 1];
        int run = carry + wbase + x - local;
#pragma unroll
        for (int j = 0; j < 4; j++) {
            int i = i0 + j;
            if (i < N_NODES) {
                g_cnt[i] = run;
                g_off[i + 1] = run + v[j];
            }
            run += v[j];
        }
        __syncthreads();
        if (tid == 0) carry += wsum[31];
        __syncthreads();
    }
}

__global__ void scatter_kernel(const float* __restrict__ w, const int* __restrict__ src,
                               const int* __restrict__ dst, int E) {
    int i = blockIdx.x * blockDim.x + threadIdx.x;
    if (i >= E) return;
    int d = dst[i];
    int pos = atomicAdd(&g_cnt[d], 1);
    g_edge[pos] = make_uint2((uint32_t)src[i], __float_as_uint(w[i]));
}

// ================= gather (4x unroll) + per-block BN1 params + fold -> fp16 agg image =================
__global__ void gather_kernel(const float* __restrict__ gamma, const float* __restrict__ beta) {
    __shared__ __align__(16) float s_a[128];
    __shared__ __align__(16) float s_b[128];
    int tid = threadIdx.x;
    if (tid < 128) {
        float mean = g_sum1[tid] * (1.f / N_NODES);
        float var = g_sq1[tid] * (1.f / N_NODES) - mean * mean;
        float av = gamma[tid] * rsqrtf(var + EPS);
        s_a[tid] = av;
        s_b[tid] = beta[tid] - mean * av;
    }
    __syncthreads();

    int gw = (blockIdx.x * blockDim.x + tid) >> 5;
    int lane = tid & 31;
    if (gw >= N_NODES) return;
    int beg = g_off[gw], end = g_off[gw + 1];
    float a0 = 0.f, a1v = 0.f, a2v = 0.f, a3v = 0.f;
    float den = 0.f;
    int j = beg;
    for (; j + 3 < end; j += 4) {
        uint2 e0 = g_edge[j];
        uint2 e1 = g_edge[j + 1];
        uint2 e2 = g_edge[j + 2];
        uint2 e3 = g_edge[j + 3];
        uint2 h0 = ((const uint2*)(g_h16 + (size_t)e0.x * 128))[lane];
        uint2 h1 = ((const uint2*)(g_h16 + (size_t)e1.x * 128))[lane];
        uint2 h2 = ((const uint2*)(g_h16 + (size_t)e2.x * 128))[lane];
        uint2 h3 = ((const uint2*)(g_h16 + (size_t)e3.x * 128))[lane];
        float w0 = __uint_as_float(e0.y), w1 = __uint_as_float(e1.y);
        float w2 = __uint_as_float(e2.y), w3 = __uint_as_float(e3.y);
        float2 p00 = __half22float2(*(const __half2*)&h0.x);
        float2 p01 = __half22float2(*(const __half2*)&h0.y);
        float2 p10 = __half22float2(*(const __half2*)&h1.x);
        float2 p11 = __half22float2(*(const __half2*)&h1.y);
        float2 p20 = __half22float2(*(const __half2*)&h2.x);
        float2 p21 = __half22float2(*(const __half2*)&h2.y);
        float2 p30 = __half22float2(*(const __half2*)&h3.x);
        float2 p31 = __half22float2(*(const __half2*)&h3.y);
        a0  += w0 * p00.x + w1 * p10.x + w2 * p20.x + w3 * p30.x;
        a1v += w0 * p00.y + w1 * p10.y + w2 * p20.y + w3 * p30.y;
        a2v += w0 * p01.x + w1 * p11.x + w2 * p21.x + w3 * p31.x;
        a3v += w0 * p01.y + w1 * p11.y + w2 * p21.y + w3 * p31.y;
        den += w0 + w1 + w2 + w3;
    }
    for (; j < end; j++) {
        uint2 e = g_edge[j];
        float we = __uint_as_float(e.y);
        uint2 hp = ((const uint2*)(g_h16 + (size_t)e.x * 128))[lane];
        float2 f0 = __half22float2(*(const __half2*)&hp.x);
        float2 f1 = __half22float2(*(const __half2*)&hp.y);
        a0 += we * f0.x; a1v += we * f0.y;
        a2v += we * f1.x; a3v += we * f1.y;
        den += we;
    }
    float4 a = *(const float4*)&s_a[lane * 4];
    float4 b = *(const float4*)&s_b[lane * 4];
    float4 v;
    if (den != 0.f) {
        float inv = 1.f / den;
        v.x = a.x * (a0 * inv) + b.x;
        v.y = a.y * (a1v * inv) + b.y;
        v.z = a.z * (a2v * inv) + b.z;
        v.w = a.w * (a3v * inv) + b.w;
    } else {
        uint2 hp = ((const uint2*)(g_h16 + (size_t)gw * 128))[lane];
        float2 f0 = __half22float2(*(const __half2*)&hp.x);
        float2 f1 = __half22float2(*(const __half2*)&hp.y);
        v.x = a.x * f0.x + b.x;
        v.y = a.y * f0.y + b.y;
        v.z = a.z * f1.x + b.z;
        v.w = a.w * f1.y + b.w;
    }
    __half2 p0 = __floats2half2_rn(v.x, v.y);
    __half2 p1 = __floats2half2_rn(v.z, v.w);
    int chunk = lane >> 4;
    int cin = (lane * 4) & 63;
    *(uint2*)(&g_aggimg[chunk][(size_t)gw * TROW + cin * 2]) =
        make_uint2(*(uint32_t*)&p0, *(uint32_t*)&p1);
}

// ================= final: per-block BN2 params + BN2 + L2 normalize (fp16 input) =================
__global__ void final_kernel(float* __restrict__ out, const float* __restrict__ gamma,
                             const float* __restrict__ beta) {
    __shared__ __align__(16) float s_a[128];
    __shared__ __align__(16) float s_b[128];
    int tid = threadIdx.x;
    if (tid < 128) {
        float mean = g_sum2[tid] * (1.f / N_NODES);
        float var = g_sq2[tid] * (1.f / N_NODES) - mean * mean;
        float av = gamma[tid] * rsqrtf(var + EPS);
        s_a[tid] = av;
        s_b[tid] = beta[tid] - mean * av;
    }
    __syncthreads();

    int gw = (blockIdx.x * blockDim.x + tid) >> 5;
    int lane = tid & 31;
    if (gw >= N_NODES) return;
    float4 a = *(const float4*)&s_a[lane * 4];
    float4 b = *(const float4*)&s_b[lane * 4];
    uint2 hp = ((const uint2*)(g_rst16 + (size_t)gw * 128))[lane];
    float2 f0 = __half22float2(*(const __half2*)&hp.x);
    float2 f1 = __half22float2(*(const __half2*)&hp.y);
    float4 v;
    v.x = f0.x * a.x + b.x; v.y = f0.y * a.y + b.y;
    v.z = f1.x * a.z + b.z; v.w = f1.y * a.w + b.w;
    float ss = v.x * v.x + v.y * v.y + v.z * v.z + v.w * v.w;
#pragma unroll
    for (int o = 16; o > 0; o >>= 1) ss += __shfl_xor_sync(0xFFFFFFFFu, ss, o);
    float norm = sqrtf(ss);
    float inv = (norm == 0.f) ? 1.f : 1.f / norm;
    v.x *= inv; v.y *= inv; v.z *= inv; v.w *= inv;
    ((float4*)out)[(size_t)gw * 32 + lane] = v;
}

extern "C" void kernel_launch(void* const* d_in, const int* in_sizes, int n_in,
                              void* d_out, int out_size) {
    const float* feat  = (const float*)d_in[0];
    const float* w     = (const float*)d_in[1];
    const float* Qw    = (const float*)d_in[2];
    const float* Qb    = (const float*)d_in[3];
    const float* Ww    = (const float*)d_in[4];
    const float* Wb    = (const float*)d_in[5];
    const float* gamma = (const float*)d_in[6];
    const float* beta  = (const float*)d_in[7];
    const int* src     = (const int*)d_in[8];
    const int* dst     = (const int*)d_in[9];
    const int E = in_sizes[1];
    float* out = (float*)d_out;

    static int smem_set = 0;
    if (!smem_set) {
        cudaFuncSetAttribute(hmma_gemm<0>, cudaFuncAttributeMaxDynamicSharedMemorySize, SM_TOTAL);
        cudaFuncSetAttribute(hmma_gemm<1>, cudaFuncAttributeMaxDynamicSharedMemorySize, SM_TOTAL);
        smem_set = 1;
    }

    const int tile_grid = (N_NODES + 127) / 128;        // 391
    const int warp_grid = (N_NODES * 32 + 255) / 256;   // 6250
    const int e_grid = (E + 255) / 256;                 // 3125

    prep_kernel<<<6250 + 192 + 196, 256>>>(feat, Qw, Ww);
    hist_kernel<<<e_grid, 256>>>(dst, E);
    prefix_kernel<<<1, 1024>>>();
    scatter_kernel<<<e_grid, 256>>>(w, src, dst, E);
    hmma_gemm<0><<<tile_grid, 256, SM_TOTAL>>>(Qb);
    stats_kernel<0><<<128, 256>>>();
    gather_kernel<<<warp_grid, 256>>>(gamma, beta);
    hmma_gemm<1><<<tile_grid, 256, SM_TOTAL>>>(Wb);
    stats_kernel<1><<<128, 256>>>();
    final_kernel<<<warp_grid, 256>>>(out, gamma, beta);
}